// round 2
// baseline (speedup 1.0000x reference)
#include <cuda_runtime.h>
#include <cuda_bf16.h>
#include <cstdint>

#define N_MAX   100000
#define E_MAX   3200000
#define C_DIM   40
#define F_DIM   128

// ---------------- scratch (device globals; no allocation) ----------------
__device__ int   g_is64;
__device__ int   g_row[E_MAX];
__device__ int   g_col[E_MAX];
__device__ float g_dinv[N_MAX];
__device__ __align__(16) float g_bufA[(size_t)N_MAX * C_DIM];
__device__ __align__(16) float g_bufB[(size_t)N_MAX * C_DIM];

// ---------------- helpers ----------------
__device__ __forceinline__ void red_add_v4(float* addr, float a, float b, float c, float d) {
    asm volatile("red.global.v4.f32.add [%0], {%1,%2,%3,%4};"
                 :: "l"(addr), "f"(a), "f"(b), "f"(c), "f"(d)
                 : "memory");
}

// ---------------- kernels ----------------

// Detect whether the edge buffer is int64 (odd 32-bit words all zero) or int32.
__global__ void k_detect(const int* __restrict__ ei32, int E) {
    if (blockIdx.x == 0 && threadIdx.x == 0) {
        int n = E < 64 ? E : 64;
        int is64 = 1;
        for (int i = 0; i < n; ++i)
            if (ei32[2 * i + 1] != 0) { is64 = 0; break; }
        g_is64 = is64;
    }
}

// Normalize edges into int32 row/col arrays regardless of input dtype.
__global__ void k_convert(const void* __restrict__ ei, int E) {
    int e = blockIdx.x * blockDim.x + threadIdx.x;
    if (e >= E) return;
    if (g_is64) {
        const long long* p = (const long long*)ei;
        g_row[e] = (int)p[e];
        g_col[e] = (int)p[(size_t)E + e];
    } else {
        const int* p = (const int*)ei;
        g_row[e] = p[e];
        g_col[e] = p[(size_t)E + e];
    }
}

// deg[i] = 1 (self loop)
__global__ void k_init_deg(float* deg, int N) {
    int i = blockIdx.x * blockDim.x + threadIdx.x;
    if (i < N) deg[i] = 1.0f;
}

// deg[col[e]] += 1
__global__ void k_count_deg(int E, float* deg) {
    int e = blockIdx.x * blockDim.x + threadIdx.x;
    if (e < E) atomicAdd(&deg[g_col[e]], 1.0f);
}

// dinv[i] = rsqrt(deg[i])   (deg >= 1 always)
__global__ void k_rsqrt(float* deg, int N) {
    int i = blockIdx.x * blockDim.x + threadIdx.x;
    if (i < N) deg[i] = rsqrtf(deg[i]);
}

// Y[n, :] = X[n, :] @ W^T     (W is [C, F] row-major)
__global__ void k_gemm(const float* __restrict__ X, const float* __restrict__ W,
                       float* __restrict__ Y, int N) {
    __shared__ float ws[C_DIM * F_DIM];   // 20.5 KB
    for (int i = threadIdx.x; i < C_DIM * F_DIM; i += blockDim.x) ws[i] = W[i];
    __syncthreads();

    int n = blockIdx.x * blockDim.x + threadIdx.x;
    if (n >= N) return;

    const float4* xp = (const float4*)(X + (size_t)n * F_DIM);
    float acc[C_DIM];
#pragma unroll
    for (int c = 0; c < C_DIM; ++c) acc[c] = 0.0f;

#pragma unroll 1
    for (int ch = 0; ch < 8; ++ch) {          // 8 chunks of 16 floats
        float4 xv[4];
#pragma unroll
        for (int j = 0; j < 4; ++j) xv[j] = xp[ch * 4 + j];
#pragma unroll
        for (int c = 0; c < C_DIM; ++c) {
            const float4* wp = (const float4*)(ws + c * F_DIM + ch * 16);
            float s = acc[c];
#pragma unroll
            for (int j = 0; j < 4; ++j) {
                float4 w = wp[j];
                s += xv[j].x * w.x + xv[j].y * w.y + xv[j].z * w.z + xv[j].w * w.w;
            }
            acc[c] = s;
        }
    }

    float4* yp = (float4*)(Y + (size_t)n * C_DIM);
#pragma unroll
    for (int k = 0; k < 10; ++k)
        yp[k] = make_float4(acc[4 * k], acc[4 * k + 1], acc[4 * k + 2], acc[4 * k + 3]);
}

// dst[n, :] = dinv[n]^2 * src[n, :]   (self-loop term, also initializes dst)
__global__ void k_self_init(const float4* __restrict__ src, float4* __restrict__ dst,
                            const float* __restrict__ dinv, int N) {
    int i = blockIdx.x * blockDim.x + threadIdx.x;   // over N*10 float4s
    if (i >= N * 10) return;
    int n = i / 10;
    float s = dinv[n];
    s = s * s;
    float4 v = src[i];
    dst[i] = make_float4(s * v.x, s * v.y, s * v.z, s * v.w);
}

// dst[col] += dinv[row]*dinv[col] * src[row]   per edge
__global__ void k_scatter(int E, const float* __restrict__ dinv,
                          const float4* __restrict__ src, float* __restrict__ dst) {
    int e = blockIdx.x * blockDim.x + threadIdx.x;
    if (e >= E) return;
    int r = g_row[e];
    int c = g_col[e];
    float nrm = dinv[r] * dinv[c];
    const float4* s = src + (size_t)r * 10;
    float* d = dst + (size_t)c * C_DIM;
#pragma unroll
    for (int k = 0; k < 10; ++k) {
        float4 v = s[k];
        red_add_v4(d + k * 4, nrm * v.x, nrm * v.y, nrm * v.z, nrm * v.w);
    }
}

// out[n, :] = log_softmax(src[n, :] + bias)
__global__ void k_lsm(const float* __restrict__ src, const float* __restrict__ bias,
                      float* __restrict__ out, int N) {
    int n = blockIdx.x * blockDim.x + threadIdx.x;
    if (n >= N) return;
    float z[C_DIM];
    const float4* s = (const float4*)(src + (size_t)n * C_DIM);
#pragma unroll
    for (int k = 0; k < 10; ++k) {
        float4 v = s[k];
        z[4 * k + 0] = v.x + bias[4 * k + 0];
        z[4 * k + 1] = v.y + bias[4 * k + 1];
        z[4 * k + 2] = v.z + bias[4 * k + 2];
        z[4 * k + 3] = v.w + bias[4 * k + 3];
    }
    float m = z[0];
#pragma unroll
    for (int c = 1; c < C_DIM; ++c) m = fmaxf(m, z[c]);
    float sum = 0.0f;
#pragma unroll
    for (int c = 0; c < C_DIM; ++c) sum += expf(z[c] - m);
    float l = m + logf(sum);
    float4* o = (float4*)(out + (size_t)n * C_DIM);
#pragma unroll
    for (int k = 0; k < 10; ++k)
        o[k] = make_float4(z[4 * k] - l, z[4 * k + 1] - l, z[4 * k + 2] - l, z[4 * k + 3] - l);
}

// ---------------- launch ----------------
extern "C" void kernel_launch(void* const* d_in, const int* in_sizes, int n_in,
                              void* d_out, int out_size) {
    const float* X    = (const float*)d_in[0];      // [N, 128]
    const float* W    = (const float*)d_in[1];      // [40, 128]
    const float* bias = (const float*)d_in[2];      // [40]
    const void*  ei   = d_in[3];                    // [2, E] int32 or int64
    (void)n_in;

    const int N = in_sizes[0] / F_DIM;
    const int E = in_sizes[3] / 2;
    float* out = (float*)d_out;
    (void)out_size;

    float* dinv = g_dinv;
    float* bufA = g_bufA;
    float* bufB = g_bufB;

    const int TB = 256;
    dim3 gN((N + TB - 1) / TB);
    dim3 gE((E + TB - 1) / TB);
    dim3 gV((N * 10 + TB - 1) / TB);

    // edge dtype detection + normalization to int32
    k_detect<<<1, 32>>>((const int*)ei, E);
    k_convert<<<gE, TB>>>(ei, E);

    // degree + normalization
    k_init_deg<<<gN, TB>>>(dinv, N);
    k_count_deg<<<gE, TB>>>(E, dinv);
    k_rsqrt<<<gN, TB>>>(dinv, N);

    // projection first (feature dim 128 -> 40), then propagate
    k_gemm<<<gN, TB>>>(X, W, bufA, N);

    // hop 1: bufA -> bufB
    k_self_init<<<gV, TB>>>((const float4*)bufA, (float4*)bufB, dinv, N);
    k_scatter<<<gE, TB>>>(E, dinv, (const float4*)bufA, bufB);

    // hop 2: bufB -> bufA
    k_self_init<<<gV, TB>>>((const float4*)bufB, (float4*)bufA, dinv, N);
    k_scatter<<<gE, TB>>>(E, dinv, (const float4*)bufB, bufA);

    // bias + log_softmax
    k_lsm<<<gN, TB>>>(bufA, bias, out, N);
}

// round 3
// speedup vs baseline: 7.5245x; 7.5245x over previous
#include <cuda_runtime.h>
#include <cuda_bf16.h>
#include <cstdint>

#define N_MAX   100000
#define E_MAX   3200000
#define C_DIM   40
#define F_DIM   128
#define SCAN_T  1024

// ---------------- scratch (device globals; no allocation) ----------------
__device__ int   g_is64;
__device__ int   g_row[E_MAX];
__device__ int   g_col[E_MAX];
__device__ int   g_cnt[N_MAX];
__device__ int   g_off[N_MAX + 1];
__device__ int   g_cur[N_MAX];
__device__ __align__(8)  int2  g_adj[E_MAX];      // {nbr, norm-as-int}
__device__ float g_dinv[N_MAX];
__device__ __align__(16) float g_bufA[(size_t)N_MAX * C_DIM];
__device__ __align__(16) float g_bufB[(size_t)N_MAX * C_DIM];

// ---------------- kernels ----------------

// Detect whether the edge buffer is int64 (odd 32-bit words all zero) or int32.
__global__ void k_detect(const int* __restrict__ ei32, int E) {
    if (blockIdx.x == 0 && threadIdx.x == 0) {
        int n = E < 64 ? E : 64;
        int is64 = 1;
        for (int i = 0; i < n; ++i)
            if (ei32[2 * i + 1] != 0) { is64 = 0; break; }
        g_is64 = is64;
    }
}

__global__ void k_zero_cnt(int N) {
    int i = blockIdx.x * blockDim.x + threadIdx.x;
    if (i < N) g_cnt[i] = 0;
}

// Normalize edges to int32 + histogram of col (in-degree, no self-loop yet).
__global__ void k_convert_hist(const void* __restrict__ ei, int E) {
    int e = blockIdx.x * blockDim.x + threadIdx.x;
    if (e >= E) return;
    int r, c;
    if (g_is64) {
        const long long* p = (const long long*)ei;
        r = (int)p[e];
        c = (int)p[(size_t)E + e];
    } else {
        const int* p = (const int*)ei;
        r = p[e];
        c = p[(size_t)E + e];
    }
    g_row[e] = r;
    g_col[e] = c;
    atomicAdd(&g_cnt[c], 1);
}

// Single-block scan: off = exclusive_prefix(cnt); cur = off; dinv = rsqrt(cnt+1).
__global__ void k_scan(int N) {
    __shared__ int ssum[SCAN_T];
    int t = threadIdx.x;
    int chunk = (N + SCAN_T - 1) / SCAN_T;
    int lo = t * chunk;
    int hi = lo + chunk < N ? lo + chunk : N;

    int s = 0;
    for (int i = lo; i < hi; ++i) s += g_cnt[i];
    ssum[t] = s;
    __syncthreads();

    // inclusive Hillis-Steele scan over block sums
    for (int d = 1; d < SCAN_T; d <<= 1) {
        int tmp = (t >= d) ? ssum[t - d] : 0;
        __syncthreads();
        ssum[t] += tmp;
        __syncthreads();
    }

    int run = ssum[t] - s;  // exclusive base for this chunk
    for (int i = lo; i < hi; ++i) {
        int c = g_cnt[i];
        g_off[i] = run;
        g_cur[i] = run;
        g_dinv[i] = rsqrtf((float)(c + 1));
        run += c;
    }
    if (t == SCAN_T - 1) g_off[N] = ssum[SCAN_T - 1];
}

// Fill CSR: adj[pos] = {row, dinv[row]*dinv[col]} grouped by col.
__global__ void k_fill(int E) {
    int e = blockIdx.x * blockDim.x + threadIdx.x;
    if (e >= E) return;
    int r = g_row[e];
    int c = g_col[e];
    int p = atomicAdd(&g_cur[c], 1);
    float w = g_dinv[r] * g_dinv[c];
    g_adj[p] = make_int2(r, __float_as_int(w));
}

// Y[n, :] = X[n, :] @ W^T     (W is [C, F] row-major)
__global__ void k_gemm(const float* __restrict__ X, const float* __restrict__ W,
                       float* __restrict__ Y, int N) {
    __shared__ float ws[C_DIM * F_DIM];   // 20.5 KB
    for (int i = threadIdx.x; i < C_DIM * F_DIM; i += blockDim.x) ws[i] = W[i];
    __syncthreads();

    int n = blockIdx.x * blockDim.x + threadIdx.x;
    if (n >= N) return;

    const float4* xp = (const float4*)(X + (size_t)n * F_DIM);
    float acc[C_DIM];
#pragma unroll
    for (int c = 0; c < C_DIM; ++c) acc[c] = 0.0f;

#pragma unroll 1
    for (int ch = 0; ch < 8; ++ch) {
        float4 xv[4];
#pragma unroll
        for (int j = 0; j < 4; ++j) xv[j] = xp[ch * 4 + j];
#pragma unroll
        for (int c = 0; c < C_DIM; ++c) {
            const float4* wp = (const float4*)(ws + c * F_DIM + ch * 16);
            float s = acc[c];
#pragma unroll
            for (int j = 0; j < 4; ++j) {
                float4 w = wp[j];
                s += xv[j].x * w.x + xv[j].y * w.y + xv[j].z * w.z + xv[j].w * w.w;
            }
            acc[c] = s;
        }
    }

    float4* yp = (float4*)(Y + (size_t)n * C_DIM);
#pragma unroll
    for (int k = 0; k < 10; ++k)
        yp[k] = make_float4(acc[4 * k], acc[4 * k + 1], acc[4 * k + 2], acc[4 * k + 3]);
}

// One hop, gather form. 5 threads per node; thread handles 8 features (2 float4).
// dst[n] = dinv[n]^2 * src[n] + sum_k w[k] * src[nbr[k]]
__global__ void k_gather(const float4* __restrict__ src, float4* __restrict__ dst, int N) {
    int t = blockIdx.x * blockDim.x + threadIdx.x;
    int n = t / 5;
    int part = t % 5;
    if (n >= N) return;

    int beg = g_off[n];
    int end = g_off[n + 1];
    float dn = g_dinv[n];
    float w0 = dn * dn;

    const float4* srow = src + (size_t)n * 10 + part * 2;
    float4 a0 = srow[0], a1 = srow[1];
    a0.x *= w0; a0.y *= w0; a0.z *= w0; a0.w *= w0;
    a1.x *= w0; a1.y *= w0; a1.z *= w0; a1.w *= w0;

    for (int k = beg; k < end; ++k) {
        int2 pr = g_adj[k];
        int   r = pr.x;
        float w = __int_as_float(pr.y);
        const float4* v = src + (size_t)r * 10 + part * 2;
        float4 v0 = v[0], v1 = v[1];
        a0.x += w * v0.x; a0.y += w * v0.y; a0.z += w * v0.z; a0.w += w * v0.w;
        a1.x += w * v1.x; a1.y += w * v1.y; a1.z += w * v1.z; a1.w += w * v1.w;
    }

    float4* drow = dst + (size_t)n * 10 + part * 2;
    drow[0] = a0;
    drow[1] = a1;
}

// out[n, :] = log_softmax(src[n, :] + bias)
__global__ void k_lsm(const float* __restrict__ src, const float* __restrict__ bias,
                      float* __restrict__ out, int N) {
    int n = blockIdx.x * blockDim.x + threadIdx.x;
    if (n >= N) return;
    float z[C_DIM];
    const float4* s = (const float4*)(src + (size_t)n * C_DIM);
#pragma unroll
    for (int k = 0; k < 10; ++k) {
        float4 v = s[k];
        z[4 * k + 0] = v.x + bias[4 * k + 0];
        z[4 * k + 1] = v.y + bias[4 * k + 1];
        z[4 * k + 2] = v.z + bias[4 * k + 2];
        z[4 * k + 3] = v.w + bias[4 * k + 3];
    }
    float m = z[0];
#pragma unroll
    for (int c = 1; c < C_DIM; ++c) m = fmaxf(m, z[c]);
    float sum = 0.0f;
#pragma unroll
    for (int c = 0; c < C_DIM; ++c) sum += expf(z[c] - m);
    float l = m + logf(sum);
    float4* o = (float4*)(out + (size_t)n * C_DIM);
#pragma unroll
    for (int k = 0; k < 10; ++k)
        o[k] = make_float4(z[4 * k] - l, z[4 * k + 1] - l, z[4 * k + 2] - l, z[4 * k + 3] - l);
}

// ---------------- launch ----------------
extern "C" void kernel_launch(void* const* d_in, const int* in_sizes, int n_in,
                              void* d_out, int out_size) {
    const float* X    = (const float*)d_in[0];      // [N, 128]
    const float* W    = (const float*)d_in[1];      // [40, 128]
    const float* bias = (const float*)d_in[2];      // [40]
    const void*  ei   = d_in[3];                    // [2, E] int32 or int64
    (void)n_in;

    const int N = in_sizes[0] / F_DIM;
    const int E = in_sizes[3] / 2;
    float* out = (float*)d_out;
    (void)out_size;

    const int TB = 256;
    dim3 gN((N + TB - 1) / TB);
    dim3 gE((E + TB - 1) / TB);

    // CSR build
    k_detect<<<1, 32>>>((const int*)ei, E);
    k_zero_cnt<<<gN, TB>>>(N);
    k_convert_hist<<<gE, TB>>>(ei, E);
    k_scan<<<1, SCAN_T>>>(N);
    k_fill<<<gE, TB>>>(E);

    // projection first (128 -> 40), then propagate
    k_gemm<<<gN, TB>>>(X, W, g_bufA, N);

    // gather hops (no atomics)
    const int GB = 320;                       // 64 nodes per block (5 thr/node)
    dim3 gG(((size_t)N * 5 + GB - 1) / GB);
    k_gather<<<gG, GB>>>((const float4*)g_bufA, (float4*)g_bufB, N);
    k_gather<<<gG, GB>>>((const float4*)g_bufB, (float4*)g_bufA, N);

    // bias + log_softmax
    k_lsm<<<gN, TB>>>(g_bufA, bias, out, N);
}